// round 3
// baseline (speedup 1.0000x reference)
#include <cuda_runtime.h>
#include <cstdint>

// Scratch for per-block partial sums of p_target (allocation-free rule:
// __device__ global array).
#define MAX_PARTIALS 32768
__device__ float g_partials[MAX_PARTIALS];

// Fast exp(x) for |x| < ~80: round-to-int trick + degree-4 Taylor of 2^f.
// FFMA-only (no MUFU). Rel err ~4e-5 on f in [-0.5, 0.5].
__device__ __forceinline__ float fexp(float x) {
    // z = round(x*log2e) embedded in mantissa of 1.5*2^23
    float z  = fmaf(x, 1.4426950408889634f, 12582912.0f);
    int   n  = __float_as_int(z) - 0x4B400000;      // integer part
    float nf = z - 12582912.0f;                     // same, as float
    float f  = fmaf(x, 1.4426950408889634f, -nf);   // frac in [-0.5, 0.5]
    // 2^f, Taylor deg-4 in ln2*f
    float p = fmaf(f,
               fmaf(f,
                fmaf(f,
                 fmaf(f, 0.009618129842071848f, 0.05550410866482158f),
                 0.24022650695910072f),
                0.6931471805599453f),
               1.0f);
    // scale by 2^n via exponent-field add (p in [0.70,1.42], no denormal risk)
    return __int_as_float(__float_as_int(p) + (n << 23));
}

// One warp per row: single-pass sum(exp(x)), gather exp(x_target),
// p_t = exp(x_t)/sum. Block writes sum of its rows' p_t to g_partials.
__global__ void __launch_bounds__(256)
mae_row_kernel(const float* __restrict__ logits,
               const int* __restrict__ targets,   // int32 (JAX demotes int64)
               int B, int C)
{
    const int lane = threadIdx.x & 31;
    const int warp = threadIdx.x >> 5;
    const int row  = blockIdx.x * (blockDim.x >> 5) + warp;

    __shared__ float s_p[8];

    float p_t = 0.0f;
    if (row < B) {
        const size_t base = (size_t)row * (size_t)C;
        const float4* rp = reinterpret_cast<const float4*>(logits + base);
        const int C4 = C >> 2;

        float acc = 0.0f;
        #pragma unroll 4
        for (int j = lane; j < C4; j += 32) {
            float4 v = rp[j];
            acc += fexp(v.x);
            acc += fexp(v.y);
            acc += fexp(v.z);
            acc += fexp(v.w);
        }
        // scalar tail (C % 4 != 0; unused for C=1000 but kept general)
        for (int c = (C4 << 2) + lane; c < C; c += 32)
            acc += fexp(logits[base + c]);

        // warp butterfly reduce -> all lanes hold full row sum
        #pragma unroll
        for (int o = 16; o; o >>= 1)
            acc += __shfl_xor_sync(0xFFFFFFFFu, acc, o);

        if (lane == 0) {
            int t = targets[row];
            t = (t < 0) ? 0 : ((t >= C) ? C - 1 : t);   // defensive clamp
            float xt = logits[base + (size_t)t];
            p_t = fexp(xt) / acc;
        }
    }

    if (lane == 0) s_p[warp] = p_t;
    __syncthreads();

    if (threadIdx.x == 0) {
        float s = 0.0f;
        const int nw = blockDim.x >> 5;
        #pragma unroll
        for (int w = 0; w < 8; w++)
            if (w < nw) s += s_p[w];
        g_partials[blockIdx.x] = s;
    }
}

// Deterministic final reduction of block partials -> scalar loss.
__global__ void __launch_bounds__(1024)
mae_finalize_kernel(float* __restrict__ out, int nparts, float invB)
{
    __shared__ float sh[32];
    float s = 0.0f;
    for (int i = threadIdx.x; i < nparts; i += blockDim.x)
        s += g_partials[i];

    #pragma unroll
    for (int o = 16; o; o >>= 1)
        s += __shfl_xor_sync(0xFFFFFFFFu, s, o);
    if ((threadIdx.x & 31) == 0) sh[threadIdx.x >> 5] = s;
    __syncthreads();

    if (threadIdx.x < 32) {
        float v = (threadIdx.x < (blockDim.x >> 5)) ? sh[threadIdx.x] : 0.0f;
        #pragma unroll
        for (int o = 16; o; o >>= 1)
            v += __shfl_xor_sync(0xFFFFFFFFu, v, o);
        if (threadIdx.x == 0)
            out[0] = 2.0f - 2.0f * v * invB;
    }
}

extern "C" void kernel_launch(void* const* d_in, const int* in_sizes, int n_in,
                              void* d_out, int out_size)
{
    const float* logits  = (const float*)d_in[0];
    const int*   targets = (const int*)d_in[1];
    float*       out     = (float*)d_out;

    const int B = in_sizes[1];
    const int C = in_sizes[0] / B;

    const int rows_per_block = 8;                      // 256 threads, warp/row
    int grid = (B + rows_per_block - 1) / rows_per_block;
    if (grid > MAX_PARTIALS) grid = MAX_PARTIALS;      // safety

    mae_row_kernel<<<grid, 256>>>(logits, targets, B, C);
    mae_finalize_kernel<<<1, 1024>>>(out, grid, 1.0f / (float)B);
}